// round 11
// baseline (speedup 1.0000x reference)
#include <cuda_runtime.h>
#include <cuda_fp16.h>
#include <cstdint>

#define NEDGES 2000000
#define TILE_M 256
#define NTILES ((NEDGES + TILE_M - 1) / TILE_M)
#define TPB 512

// X, Y: [256 rows][136 fp16] stride 272 B (17*16: conflict-free ldmatrix)
#define ROWB 272
#define SM_X  0                 // 69632 B
#define SM_Y  69632             // 69632 B
#define SM_P  139264            // float[2][256][2] = 4096 B
#define SM_B4 143360            // float[2]
#define SMEM_BYTES 143424

#define BRANCH_BAR(b) \
    asm volatile("bar.sync %0, %1;" :: "r"(1 + (b)), "r"(256) : "memory")

__device__ __forceinline__ uint32_t smem_u32(const void* p) {
    uint32_t a;
    asm("{ .reg .u64 t; cvta.to.shared.u64 t, %1; cvt.u32.u64 %0, t; }" : "=r"(a) : "l"(p));
    return a;
}
__device__ __forceinline__ float lrelu(float z) { return fmaxf(z, 0.01f * z); }

// pack 2 f32 -> fp16x2 (a in low half)
__device__ __forceinline__ uint32_t pkh2(float a, float b) {
    __half2 h = __floats2half2_rn(a, b);
    return *(uint32_t*)&h;
}

__device__ __forceinline__ void ldsm4(uint32_t addr, uint32_t& a0, uint32_t& a1,
                                      uint32_t& a2, uint32_t& a3) {
    asm volatile("ldmatrix.sync.aligned.m8n8.x4.shared.b16 {%0,%1,%2,%3}, [%4];"
                 : "=r"(a0), "=r"(a1), "=r"(a2), "=r"(a3) : "r"(addr));
}
__device__ __forceinline__ void mma16816(float* d, uint32_t a0, uint32_t a1,
                                         uint32_t a2, uint32_t a3,
                                         uint32_t b0, uint32_t b1) {
    asm volatile(
        "mma.sync.aligned.m16n8k16.row.col.f32.f16.f16.f32 "
        "{%0,%1,%2,%3}, {%4,%5,%6,%7}, {%8,%9}, {%0,%1,%2,%3};"
        : "+f"(d[0]), "+f"(d[1]), "+f"(d[2]), "+f"(d[3])
        : "r"(a0), "r"(a1), "r"(a2), "r"(a3), "r"(b0), "r"(b1));
}

// 8x8 B fragment (col-major k8 x n8) from global W[k][n], fp16 (hi only)
__device__ __forceinline__ uint32_t make_hfrag(const float* __restrict__ W, int ldn,
                                               int k0, int n0, int lane) {
    int g = lane >> 2, tg = lane & 3;
    const float* p = W + (size_t)(k0 + tg * 2) * ldn + (n0 + g);
    return pkh2(p[0], p[ldn]);
}

__global__ void __launch_bounds__(TPB, 1)
regressor_mma_kernel(const float* __restrict__ x_src,
                     const float* __restrict__ x_dst,
                     const int* __restrict__ eidx,
                     const float* __restrict__ ew1, const float* __restrict__ eb1,
                     const float* __restrict__ ww1, const float* __restrict__ wb1,
                     const float* __restrict__ ew2, const float* __restrict__ eb2,
                     const float* __restrict__ ww2, const float* __restrict__ wb2,
                     const float* __restrict__ ew3, const float* __restrict__ eb3,
                     const float* __restrict__ ww3, const float* __restrict__ wb3,
                     const float* __restrict__ ew4, const float* __restrict__ eb4,
                     const float* __restrict__ ww4, const float* __restrict__ wb4,
                     float* __restrict__ out) {
    extern __shared__ char smem[];
    const uint32_t smb = smem_u32(smem);
    const int tid = threadIdx.x;
    const int wid = tid >> 5, lane = tid & 31;

    const int branch = wid >> 3;           // 0 = exists, 1 = weight
    const int w8 = wid & 7;
    const int mh = w8 >> 2;                // L1/L2 m-half (8 mt each of 16)
    const int nL = (w8 & 3) * 16;          // L1/L2 16-col n-slice of branch
    const int mg = w8 >> 1;                // L3 m-group (4 mt each)
    const int ns3 = w8 & 1;                // L3 n-slice index
    const int n3 = ns3 * 16;               // L3 16-col n-slice

    // ---------- per-warp weight fragments (fp16 hi, registers) ----------
    const float* W1 = branch ? ww1 : ew1;  // [128][64]
    const float* W2 = branch ? ww2 : ew2;  // [64][64]
    const float* W3 = branch ? ww3 : ew3;  // [64][32]
    const float* B1 = branch ? wb1 : eb1;
    const float* B2 = branch ? wb2 : eb2;
    const float* B3 = branch ? wb3 : eb3;
    const float* W4 = branch ? ww4 : ew4;

    uint32_t B1h[8][2][2];
#pragma unroll
    for (int kt = 0; kt < 8; kt++)
#pragma unroll
        for (int nt = 0; nt < 2; nt++)
#pragma unroll
            for (int r = 0; r < 2; r++)
                B1h[kt][nt][r] = make_hfrag(W1, 64, kt * 16 + r * 8, nL + nt * 8, lane);

    uint32_t B2h[4][2][2];
#pragma unroll
    for (int kt = 0; kt < 4; kt++)
#pragma unroll
        for (int nt = 0; nt < 2; nt++)
#pragma unroll
            for (int r = 0; r < 2; r++)
                B2h[kt][nt][r] = make_hfrag(W2, 64, kt * 16 + r * 8, nL + nt * 8, lane);

    uint32_t B3h[4][2][2];
#pragma unroll
    for (int kt = 0; kt < 4; kt++)
#pragma unroll
        for (int nt = 0; nt < 2; nt++)
#pragma unroll
            for (int r = 0; r < 2; r++)
                B3h[kt][nt][r] = make_hfrag(W3, 32, kt * 16 + r * 8, n3 + nt * 8, lane);

    // per-thread biases / final weights for covered columns
    float b1v[2][2], b2v[2][2], b3v[2][2], w4v[2][2];
#pragma unroll
    for (int nt = 0; nt < 2; nt++)
#pragma unroll
        for (int j = 0; j < 2; j++) {
            int c = nL + nt * 8 + (lane & 3) * 2 + j;
            b1v[nt][j] = B1[c];
            b2v[nt][j] = B2[c];
            int c3 = n3 + nt * 8 + (lane & 3) * 2 + j;
            b3v[nt][j] = B3[c3];
            w4v[nt][j] = W4[c3];
        }
    if (tid == 0) {
        *(float*)(smem + SM_B4 + 0) = eb4[0];
        *(float*)(smem + SM_B4 + 4) = wb4[0];
    }
    __syncthreads();

    const uint32_t xb = smb + SM_X;
    const uint32_t yb = smb + SM_Y;

    for (int t = blockIdx.x; t < NTILES; t += gridDim.x) {
        // ===== gather: warp w owns edges [16w,16w+16); lanes 0-15 src, 16-31 dst =====
        {
            const int half = lane >> 4;
            const int c16 = lane & 15;
#pragma unroll 4
            for (int i = 0; i < 16; i++) {
                int m = wid * 16 + i;
                int e = t * TILE_M + m;
                int idx = 0;
                if (e < NEDGES) idx = half ? eidx[NEDGES + e] : eidx[e];
                const float* row = (half ? x_dst : x_src) + (size_t)idx * 64;
                float4 v = ((const float4*)row)[c16];
                uint32_t h0 = pkh2(v.x, v.y);
                uint32_t h1 = pkh2(v.z, v.w);
                uint32_t off = (uint32_t)m * ROWB + half * 128u + c16 * 8u;
                *(uint2*)(smem + SM_X + off) = make_uint2(h0, h1);
            }
        }
        __syncthreads();

        // ===== L1: X[256x128] -> Y[256x128]; warp: m-half, 16-col slice =====
        {
            const int colout = branch * 64 + nL;
#pragma unroll 1
            for (int i = 0; i < 8; i++) {
                int m0 = (mh * 8 + i) * 16;
                float aP[2][4] = {};
                uint32_t arow = (uint32_t)(m0 + (lane & 15)) * ROWB + (lane >> 4) * 16u;
#pragma unroll
                for (int kt = 0; kt < 8; kt++) {
                    uint32_t h0, h1, h2, h3;
                    ldsm4(xb + arow + kt * 32u, h0, h1, h2, h3);
                    mma16816(aP[0], h0, h1, h2, h3, B1h[kt][0][0], B1h[kt][0][1]);
                    mma16816(aP[1], h0, h1, h2, h3, B1h[kt][1][0], B1h[kt][1][1]);
                }
#pragma unroll
                for (int nt = 0; nt < 2; nt++) {
                    float v0 = lrelu(aP[nt][0] + b1v[nt][0]);
                    float v1 = lrelu(aP[nt][1] + b1v[nt][1]);
                    float v2 = lrelu(aP[nt][2] + b1v[nt][0]);
                    float v3 = lrelu(aP[nt][3] + b1v[nt][1]);
                    uint32_t col2 = (uint32_t)(colout + nt * 8 + (lane & 3) * 2) * 2u;
                    uint32_t o0 = (uint32_t)(m0 + (lane >> 2)) * ROWB + col2;
                    uint32_t o1 = (uint32_t)(m0 + 8 + (lane >> 2)) * ROWB + col2;
                    *(uint32_t*)(smem + SM_Y + o0) = pkh2(v0, v1);
                    *(uint32_t*)(smem + SM_Y + o1) = pkh2(v2, v3);
                }
            }
        }
        BRANCH_BAR(branch);

        // ===== L2: Y (cols branch*64..) -> X (cols branch*64..) =====
        {
            const int colout = branch * 64 + nL;
            const uint32_t abase = (uint32_t)branch * 128u;
#pragma unroll 1
            for (int i = 0; i < 8; i++) {
                int m0 = (mh * 8 + i) * 16;
                float aP[2][4] = {};
                uint32_t arow = (uint32_t)(m0 + (lane & 15)) * ROWB + abase + (lane >> 4) * 16u;
#pragma unroll
                for (int kt = 0; kt < 4; kt++) {
                    uint32_t h0, h1, h2, h3;
                    ldsm4(yb + arow + kt * 32u, h0, h1, h2, h3);
                    mma16816(aP[0], h0, h1, h2, h3, B2h[kt][0][0], B2h[kt][0][1]);
                    mma16816(aP[1], h0, h1, h2, h3, B2h[kt][1][0], B2h[kt][1][1]);
                }
#pragma unroll
                for (int nt = 0; nt < 2; nt++) {
                    float v0 = lrelu(aP[nt][0] + b2v[nt][0]);
                    float v1 = lrelu(aP[nt][1] + b2v[nt][1]);
                    float v2 = lrelu(aP[nt][2] + b2v[nt][0]);
                    float v3 = lrelu(aP[nt][3] + b2v[nt][1]);
                    uint32_t col2 = (uint32_t)(colout + nt * 8 + (lane & 3) * 2) * 2u;
                    uint32_t o0 = (uint32_t)(m0 + (lane >> 2)) * ROWB + col2;
                    uint32_t o1 = (uint32_t)(m0 + 8 + (lane >> 2)) * ROWB + col2;
                    *(uint32_t*)(smem + SM_X + o0) = pkh2(v0, v1);
                    *(uint32_t*)(smem + SM_X + o1) = pkh2(v2, v3);
                }
            }
        }
        BRANCH_BAR(branch);

        // ===== L3 + L4: X (cols branch*64..) -> partials in P =====
        {
            const uint32_t abase = (uint32_t)branch * 128u;
            float* P = (float*)(smem + SM_P);
#pragma unroll 1
            for (int i = 0; i < 4; i++) {
                int m0 = (mg * 4 + i) * 16;
                float aP[2][4] = {};
                uint32_t arow = (uint32_t)(m0 + (lane & 15)) * ROWB + abase + (lane >> 4) * 16u;
#pragma unroll
                for (int kt = 0; kt < 4; kt++) {
                    uint32_t h0, h1, h2, h3;
                    ldsm4(xb + arow + kt * 32u, h0, h1, h2, h3);
                    mma16816(aP[0], h0, h1, h2, h3, B3h[kt][0][0], B3h[kt][0][1]);
                    mma16816(aP[1], h0, h1, h2, h3, B3h[kt][1][0], B3h[kt][1][1]);
                }
                float p0 = 0.0f, p1 = 0.0f;
#pragma unroll
                for (int nt = 0; nt < 2; nt++) {
                    p0 += lrelu(aP[nt][0] + b3v[nt][0]) * w4v[nt][0] +
                          lrelu(aP[nt][1] + b3v[nt][1]) * w4v[nt][1];
                    p1 += lrelu(aP[nt][2] + b3v[nt][0]) * w4v[nt][0] +
                          lrelu(aP[nt][3] + b3v[nt][1]) * w4v[nt][1];
                }
                p0 += __shfl_xor_sync(0xFFFFFFFFu, p0, 1);
                p0 += __shfl_xor_sync(0xFFFFFFFFu, p0, 2);
                p1 += __shfl_xor_sync(0xFFFFFFFFu, p1, 1);
                p1 += __shfl_xor_sync(0xFFFFFFFFu, p1, 2);
                if ((lane & 3) == 0) {
                    int r0 = m0 + (lane >> 2);
                    P[((branch << 8) + r0) * 2 + ns3] = p0;
                    P[((branch << 8) + r0 + 8) * 2 + ns3] = p1;
                }
            }
        }
        BRANCH_BAR(branch);

        // ===== final reduce + store (branch-local: tids 0-255 = branch 0) =====
        {
            int br = tid >> 8, m = tid & 255;
            int e = t * TILE_M + m;
            if (e < NEDGES) {
                float2 pv = *(const float2*)(smem + SM_P + ((br << 8) + m) * 8);
                float b4 = *(const float*)(smem + SM_B4 + br * 4);
                out[br * NEDGES + e] = pv.x + pv.y + b4;
            }
        }
        __syncthreads();
        // hazards: full sync above orders both branches' L3 X-reads and P
        // stores before the next gather overwrites X.
    }
}

extern "C" void kernel_launch(void* const* d_in, const int* in_sizes, int n_in,
                              void* d_out, int out_size) {
    const float* x_src = (const float*)d_in[0];
    const float* x_dst = (const float*)d_in[1];
    const int* eidx = (const int*)d_in[2];
    const float* ew1 = (const float*)d_in[3];
    const float* eb1 = (const float*)d_in[4];
    const float* ww1 = (const float*)d_in[5];
    const float* wb1 = (const float*)d_in[6];
    const float* ew2 = (const float*)d_in[7];
    const float* eb2 = (const float*)d_in[8];
    const float* ww2 = (const float*)d_in[9];
    const float* wb2 = (const float*)d_in[10];
    const float* ew3 = (const float*)d_in[11];
    const float* eb3 = (const float*)d_in[12];
    const float* ww3 = (const float*)d_in[13];
    const float* wb3 = (const float*)d_in[14];
    const float* ew4 = (const float*)d_in[15];
    const float* eb4 = (const float*)d_in[16];
    const float* ww4 = (const float*)d_in[17];
    const float* wb4 = (const float*)d_in[18];
    float* out = (float*)d_out;

    int nsm = 148;
    cudaDeviceGetAttribute(&nsm, cudaDevAttrMultiProcessorCount, 0);

    cudaFuncSetAttribute(regressor_mma_kernel,
                         cudaFuncAttributeMaxDynamicSharedMemorySize, SMEM_BYTES);

    regressor_mma_kernel<<<nsm, TPB, SMEM_BYTES>>>(
        x_src, x_dst, eidx, ew1, eb1, ww1, wb1, ew2, eb2, ww2, wb2,
        ew3, eb3, ww3, wb3, ew4, eb4, ww4, wb4, out);
}

// round 12
// speedup vs baseline: 1.0536x; 1.0536x over previous
#include <cuda_runtime.h>
#include <cuda_fp16.h>
#include <cstdint>

#define NEDGES 2000000
#define TILE_M 128
#define NTILES (NEDGES / TILE_M)
#define TPB 512

// staging: 2 x [128 rows][512 B f32], XOR-swizzled; X/Y: [128][136 fp16] stride 272
#define ROWB 272
#define SM_SA 0                 // 65536
#define SM_SB 65536             // 65536
#define SM_X  131072            // 34816
#define SM_Y  165888            // 34816
#define SM_P  200704            // float[2][128][2] = 2048
#define SM_B4 202752            // float[2]
#define SMEM_BYTES 202768

__device__ __forceinline__ uint32_t smem_u32(const void* p) {
    uint32_t a;
    asm("{ .reg .u64 t; cvta.to.shared.u64 t, %1; cvt.u32.u64 %0, t; }" : "=r"(a) : "l"(p));
    return a;
}
__device__ __forceinline__ float lrelu(float z) { return fmaxf(z, 0.01f * z); }

__device__ __forceinline__ uint32_t pkh2(float a, float b) {
    __half2 h = __floats2half2_rn(a, b);
    return *(uint32_t*)&h;
}

__device__ __forceinline__ void ldsm4(uint32_t addr, uint32_t& a0, uint32_t& a1,
                                      uint32_t& a2, uint32_t& a3) {
    asm volatile("ldmatrix.sync.aligned.m8n8.x4.shared.b16 {%0,%1,%2,%3}, [%4];"
                 : "=r"(a0), "=r"(a1), "=r"(a2), "=r"(a3) : "r"(addr));
}
__device__ __forceinline__ void mma16816(float* d, uint32_t a0, uint32_t a1,
                                         uint32_t a2, uint32_t a3,
                                         uint32_t b0, uint32_t b1) {
    asm volatile(
        "mma.sync.aligned.m16n8k16.row.col.f32.f16.f16.f32 "
        "{%0,%1,%2,%3}, {%4,%5,%6,%7}, {%8,%9}, {%0,%1,%2,%3};"
        : "+f"(d[0]), "+f"(d[1]), "+f"(d[2]), "+f"(d[3])
        : "r"(a0), "r"(a1), "r"(a2), "r"(a3), "r"(b0), "r"(b1));
}

__device__ __forceinline__ void cp_async16(uint32_t sa, const void* g) {
    asm volatile("cp.async.cg.shared.global [%0], [%1], 16;"
                 :: "r"(sa), "l"(g) : "memory");
}
#define CP_COMMIT() asm volatile("cp.async.commit_group;" ::: "memory")
#define CP_WAIT1()  asm volatile("cp.async.wait_group 1;" ::: "memory")

// 8x8 B fragment (col-major k8 x n8) from global W[k][n], fp16 (hi only)
__device__ __forceinline__ uint32_t make_hfrag(const float* __restrict__ W, int ldn,
                                               int k0, int n0, int lane) {
    int g = lane >> 2, tg = lane & 3;
    const float* p = W + (size_t)(k0 + tg * 2) * ldn + (n0 + g);
    return pkh2(p[0], p[ldn]);
}

__global__ void __launch_bounds__(TPB, 1)
regressor_mma_kernel(const float* __restrict__ x_src,
                     const float* __restrict__ x_dst,
                     const int* __restrict__ eidx,
                     const float* __restrict__ ew1, const float* __restrict__ eb1,
                     const float* __restrict__ ww1, const float* __restrict__ wb1,
                     const float* __restrict__ ew2, const float* __restrict__ eb2,
                     const float* __restrict__ ww2, const float* __restrict__ wb2,
                     const float* __restrict__ ew3, const float* __restrict__ eb3,
                     const float* __restrict__ ww3, const float* __restrict__ wb3,
                     const float* __restrict__ ew4, const float* __restrict__ eb4,
                     const float* __restrict__ ww4, const float* __restrict__ wb4,
                     float* __restrict__ out) {
    extern __shared__ char smem[];
    const uint32_t smb = smem_u32(smem);
    const int tid = threadIdx.x;
    const int wid = tid >> 5, lane = tid & 31;

    const int branch = wid >> 3;           // 0 = exists, 1 = weight
    const int w8 = wid & 7;
    const int mh = w8 >> 2;                // L1/L2 m-half
    const int nL = (w8 & 3) * 16;          // L1/L2 16-col n-slice of branch
    const int mg = w8 >> 1;                // L3 m-group
    const int ns3 = w8 & 1;                // L3 n-slice index
    const int n3 = ns3 * 16;

    // ---------- per-warp weight fragments (fp16 hi, registers) ----------
    const float* W1 = branch ? ww1 : ew1;
    const float* W2 = branch ? ww2 : ew2;
    const float* W3 = branch ? ww3 : ew3;
    const float* B1 = branch ? wb1 : eb1;
    const float* B2 = branch ? wb2 : eb2;
    const float* B3 = branch ? wb3 : eb3;
    const float* W4 = branch ? ww4 : ew4;

    uint32_t B1h[8][2][2];
#pragma unroll
    for (int kt = 0; kt < 8; kt++)
#pragma unroll
        for (int nt = 0; nt < 2; nt++)
#pragma unroll
            for (int r = 0; r < 2; r++)
                B1h[kt][nt][r] = make_hfrag(W1, 64, kt * 16 + r * 8, nL + nt * 8, lane);

    uint32_t B2h[4][2][2];
#pragma unroll
    for (int kt = 0; kt < 4; kt++)
#pragma unroll
        for (int nt = 0; nt < 2; nt++)
#pragma unroll
            for (int r = 0; r < 2; r++)
                B2h[kt][nt][r] = make_hfrag(W2, 64, kt * 16 + r * 8, nL + nt * 8, lane);

    uint32_t B3h[4][2][2];
#pragma unroll
    for (int kt = 0; kt < 4; kt++)
#pragma unroll
        for (int nt = 0; nt < 2; nt++)
#pragma unroll
            for (int r = 0; r < 2; r++)
                B3h[kt][nt][r] = make_hfrag(W3, 32, kt * 16 + r * 8, n3 + nt * 8, lane);

    float b1v[2][2], b2v[2][2], b3v[2][2], w4v[2][2];
#pragma unroll
    for (int nt = 0; nt < 2; nt++)
#pragma unroll
        for (int j = 0; j < 2; j++) {
            int c = nL + nt * 8 + (lane & 3) * 2 + j;
            b1v[nt][j] = B1[c];
            b2v[nt][j] = B2[c];
            int c3 = n3 + nt * 8 + (lane & 3) * 2 + j;
            b3v[nt][j] = B3[c3];
            w4v[nt][j] = W4[c3];
        }
    if (tid == 0) {
        *(float*)(smem + SM_B4 + 0) = eb4[0];
        *(float*)(smem + SM_B4 + 4) = wb4[0];
    }

    const uint32_t xb = smb + SM_X;
    const uint32_t yb = smb + SM_Y;
    const int G = gridDim.x;
    const int t0 = blockIdx.x;

    // ---- index pipeline: lane<8 holds src idx, lane 8-15 holds dst idx ----
    auto load_idx = [&](int t) -> int {
        if (t >= NTILES || lane >= 16) return 0;
        int e = t * TILE_M + wid * 8 + (lane & 7);
        return (lane < 8) ? eidx[e] : eidx[NEDGES + e];
    };
    // issue one tile's cp.async group into staging buffer sbuf
    auto issue_tile = [&](uint32_t sbuf, int idxreg, bool valid) {
        if (valid) {
            const int half = lane >> 4, c = lane & 15;
#pragma unroll
            for (int i = 0; i < 8; i++) {
                int sI = __shfl_sync(0xFFFFFFFFu, idxreg, i);
                int dI = __shfl_sync(0xFFFFFFFFu, idxreg, 8 + i);
                int r = wid * 8 + i;
                const char* g = half ? (const char*)(x_dst + (size_t)dI * 64)
                                     : (const char*)(x_src + (size_t)sI * 64);
                uint32_t sa = sbuf + (uint32_t)r * 512u +
                              ((uint32_t)((half * 16 + c) * 16) ^ ((uint32_t)(r & 7) << 4));
                cp_async16(sa, g + c * 16);
            }
        }
        CP_COMMIT();
    };

    // prologue: fetch tile t0 into S[0]; preload idx for t0+G
    int idxcur = load_idx(t0);
    issue_tile(smb + SM_SA, idxcur, t0 < NTILES);
    idxcur = load_idx(t0 + G);
    __syncthreads();           // covers B4 store too

    int s = 0;
    for (int t = t0; t < NTILES; t += G) {
        const uint32_t scur = smb + (s ? SM_SB : SM_SA);
        const uint32_t snxt = smb + (s ? SM_SA : SM_SB);

        // ===== A: prefetch next tile; pipeline indices two ahead =====
        issue_tile(snxt, idxcur, t + G < NTILES);
        idxcur = load_idx(t + 2 * G);

        // ===== B: wait current tile's staging =====
        CP_WAIT1();
        __syncthreads();

        // ===== C: convert S[s] f32 -> X fp16 =====
        {
            int m = tid & 127, q = tid >> 7;       // q in 0..3
            uint32_t srow = scur + (uint32_t)m * 512u;
            uint32_t swz = (uint32_t)(m & 7) << 4;
            uint32_t xrow = xb + (uint32_t)m * ROWB + (uint32_t)q * 64u;
#pragma unroll
            for (int j = 0; j < 4; j++) {
                float4 a = *(const float4*)(size_t)(0) ; // placeholder avoided below
                (void)a;
                float4 va = *reinterpret_cast<const float4*>(
                    smem + (srow - smb) + (((uint32_t)(q * 128 + 2 * j * 16)) ^ swz));
                float4 vb = *reinterpret_cast<const float4*>(
                    smem + (srow - smb) + (((uint32_t)(q * 128 + (2 * j + 1) * 16)) ^ swz));
                uint4 o;
                o.x = pkh2(va.x, va.y);
                o.y = pkh2(va.z, va.w);
                o.z = pkh2(vb.x, vb.y);
                o.w = pkh2(vb.z, vb.w);
                *reinterpret_cast<uint4*>(smem + (xrow - smb) + j * 16) = o;
            }
        }
        __syncthreads();

        // ===== L1: X[128x128] -> Y[128x128]; warp: m-half, 16-col slice =====
        {
            const int colout = branch * 64 + nL;
#pragma unroll 1
            for (int i = 0; i < 4; i++) {
                int m0 = (mh * 4 + i) * 16;
                float aP[2][4] = {};
                uint32_t arow = (uint32_t)(m0 + (lane & 15)) * ROWB + (lane >> 4) * 16u;
#pragma unroll
                for (int kt = 0; kt < 8; kt++) {
                    uint32_t h0, h1, h2, h3;
                    ldsm4(xb + arow + kt * 32u, h0, h1, h2, h3);
                    mma16816(aP[0], h0, h1, h2, h3, B1h[kt][0][0], B1h[kt][0][1]);
                    mma16816(aP[1], h0, h1, h2, h3, B1h[kt][1][0], B1h[kt][1][1]);
                }
#pragma unroll
                for (int nt = 0; nt < 2; nt++) {
                    float v0 = lrelu(aP[nt][0] + b1v[nt][0]);
                    float v1 = lrelu(aP[nt][1] + b1v[nt][1]);
                    float v2 = lrelu(aP[nt][2] + b1v[nt][0]);
                    float v3 = lrelu(aP[nt][3] + b1v[nt][1]);
                    uint32_t col2 = (uint32_t)(colout + nt * 8 + (lane & 3) * 2) * 2u;
                    uint32_t o0 = (uint32_t)(m0 + (lane >> 2)) * ROWB + col2;
                    uint32_t o1 = (uint32_t)(m0 + 8 + (lane >> 2)) * ROWB + col2;
                    *(uint32_t*)(smem + SM_Y + o0) = pkh2(v0, v1);
                    *(uint32_t*)(smem + SM_Y + o1) = pkh2(v2, v3);
                }
            }
        }
        __syncthreads();

        // ===== L2: Y (cols branch*64..) -> X (cols branch*64..) =====
        {
            const int colout = branch * 64 + nL;
            const uint32_t abase = (uint32_t)branch * 128u;
#pragma unroll 1
            for (int i = 0; i < 4; i++) {
                int m0 = (mh * 4 + i) * 16;
                float aP[2][4] = {};
                uint32_t arow = (uint32_t)(m0 + (lane & 15)) * ROWB + abase + (lane >> 4) * 16u;
#pragma unroll
                for (int kt = 0; kt < 4; kt++) {
                    uint32_t h0, h1, h2, h3;
                    ldsm4(yb + arow + kt * 32u, h0, h1, h2, h3);
                    mma16816(aP[0], h0, h1, h2, h3, B2h[kt][0][0], B2h[kt][0][1]);
                    mma16816(aP[1], h0, h1, h2, h3, B2h[kt][1][0], B2h[kt][1][1]);
                }
#pragma unroll
                for (int nt = 0; nt < 2; nt++) {
                    float v0 = lrelu(aP[nt][0] + b2v[nt][0]);
                    float v1 = lrelu(aP[nt][1] + b2v[nt][1]);
                    float v2 = lrelu(aP[nt][2] + b2v[nt][0]);
                    float v3 = lrelu(aP[nt][3] + b2v[nt][1]);
                    uint32_t col2 = (uint32_t)(colout + nt * 8 + (lane & 3) * 2) * 2u;
                    uint32_t o0 = (uint32_t)(m0 + (lane >> 2)) * ROWB + col2;
                    uint32_t o1 = (uint32_t)(m0 + 8 + (lane >> 2)) * ROWB + col2;
                    *(uint32_t*)(smem + SM_X + o0) = pkh2(v0, v1);
                    *(uint32_t*)(smem + SM_X + o1) = pkh2(v2, v3);
                }
            }
        }
        __syncthreads();

        // ===== L3 + L4: X (cols branch*64..) -> partials in P =====
        {
            const uint32_t abase = (uint32_t)branch * 128u;
            float* P = (float*)(smem + SM_P);
#pragma unroll 1
            for (int i = 0; i < 2; i++) {
                int m0 = (mg * 2 + i) * 16;
                float aP[2][4] = {};
                uint32_t arow = (uint32_t)(m0 + (lane & 15)) * ROWB + abase + (lane >> 4) * 16u;
#pragma unroll
                for (int kt = 0; kt < 4; kt++) {
                    uint32_t h0, h1, h2, h3;
                    ldsm4(xb + arow + kt * 32u, h0, h1, h2, h3);
                    mma16816(aP[0], h0, h1, h2, h3, B3h[kt][0][0], B3h[kt][0][1]);
                    mma16816(aP[1], h0, h1, h2, h3, B3h[kt][1][0], B3h[kt][1][1]);
                }
                float p0 = 0.0f, p1 = 0.0f;
#pragma unroll
                for (int nt = 0; nt < 2; nt++) {
                    p0 += lrelu(aP[nt][0] + b3v[nt][0]) * w4v[nt][0] +
                          lrelu(aP[nt][1] + b3v[nt][1]) * w4v[nt][1];
                    p1 += lrelu(aP[nt][2] + b3v[nt][0]) * w4v[nt][0] +
                          lrelu(aP[nt][3] + b3v[nt][1]) * w4v[nt][1];
                }
                p0 += __shfl_xor_sync(0xFFFFFFFFu, p0, 1);
                p0 += __shfl_xor_sync(0xFFFFFFFFu, p0, 2);
                p1 += __shfl_xor_sync(0xFFFFFFFFu, p1, 1);
                p1 += __shfl_xor_sync(0xFFFFFFFFu, p1, 2);
                if ((lane & 3) == 0) {
                    int r0 = m0 + (lane >> 2);
                    P[((branch << 7) + r0) * 2 + ns3] = p0;
                    P[((branch << 7) + r0 + 8) * 2 + ns3] = p1;
                }
            }
        }
        __syncthreads();

        // ===== store (256 threads) =====
        if (tid < 256) {
            int br = tid >> 7, m = tid & 127;
            float2 pv = *(const float2*)(smem + SM_P + ((br << 7) + m) * 8);
            float b4 = *(const float*)(smem + SM_B4 + br * 4);
            out[br * NEDGES + t * TILE_M + m] = pv.x + pv.y + b4;
        }
        s ^= 1;
        // hazards: next A writes S[s^1] (last read by convert two tiles back,
        // many syncs ago); next convert writes X (last read in L3 above,
        // separated by the post-L3 sync + the post-B sync).
    }
}

extern "C" void kernel_launch(void* const* d_in, const int* in_sizes, int n_in,
                              void* d_out, int out_size) {
    const float* x_src = (const float*)d_in[0];
    const float* x_dst = (const float*)d_in[1];
    const int* eidx = (const int*)d_in[2];
    const float* ew1 = (const float*)d_in[3];
    const float* eb1 = (const float*)d_in[4];
    const float* ww1 = (const float*)d_in[5];
    const float* wb1 = (const float*)d_in[6];
    const float* ew2 = (const float*)d_in[7];
    const float* eb2 = (const float*)d_in[8];
    const float* ww2 = (const float*)d_in[9];
    const float* wb2 = (const float*)d_in[10];
    const float* ew3 = (const float*)d_in[11];
    const float* eb3 = (const float*)d_in[12];
    const float* ww3 = (const float*)d_in[13];
    const float* wb3 = (const float*)d_in[14];
    const float* ew4 = (const float*)d_in[15];
    const float* eb4 = (const float*)d_in[16];
    const float* ww4 = (const float*)d_in[17];
    const float* wb4 = (const float*)d_in[18];
    float* out = (float*)d_out;

    int nsm = 148;
    cudaDeviceGetAttribute(&nsm, cudaDevAttrMultiProcessorCount, 0);

    cudaFuncSetAttribute(regressor_mma_kernel,
                         cudaFuncAttributeMaxDynamicSharedMemorySize, SMEM_BYTES);

    regressor_mma_kernel<<<nsm, TPB, SMEM_BYTES>>>(
        x_src, x_dst, eidx, ew1, eb1, ww1, wb1, ew2, eb2, ww2, wb2,
        ew3, eb3, ww3, wb3, ew4, eb4, ww4, wb4, out);
}

// round 13
// speedup vs baseline: 1.1614x; 1.1023x over previous
#include <cuda_runtime.h>
#include <cuda_fp16.h>
#include <cstdint>

#define NEDGES 2000000
#define TILE_M 128
#define NTILES (NEDGES / TILE_M)
#define TPB 256

// X, Y: [128 rows][136 fp16] stride 272 B (17*16: conflict-free ldmatrix)
#define ROWB 272
#define SM_X  0                 // 34816 B
#define SM_Y  34816             // 34816 B
#define SM_P  69632             // float[2][128][2] = 2048 B
#define SM_B4 71680             // float[2]
#define SMEM_BYTES 71744

__device__ __forceinline__ uint32_t smem_u32(const void* p) {
    uint32_t a;
    asm("{ .reg .u64 t; cvta.to.shared.u64 t, %1; cvt.u32.u64 %0, t; }" : "=r"(a) : "l"(p));
    return a;
}
__device__ __forceinline__ float lrelu(float z) { return fmaxf(z, 0.01f * z); }

// pack 2 f32 -> fp16x2 (a in low half)
__device__ __forceinline__ uint32_t pkh2(float a, float b) {
    __half2 h = __floats2half2_rn(a, b);
    return *(uint32_t*)&h;
}

__device__ __forceinline__ void ldsm4(uint32_t addr, uint32_t& a0, uint32_t& a1,
                                      uint32_t& a2, uint32_t& a3) {
    asm volatile("ldmatrix.sync.aligned.m8n8.x4.shared.b16 {%0,%1,%2,%3}, [%4];"
                 : "=r"(a0), "=r"(a1), "=r"(a2), "=r"(a3) : "r"(addr));
}
__device__ __forceinline__ void mma16816(float* d, uint32_t a0, uint32_t a1,
                                         uint32_t a2, uint32_t a3,
                                         uint32_t b0, uint32_t b1) {
    asm volatile(
        "mma.sync.aligned.m16n8k16.row.col.f32.f16.f16.f32 "
        "{%0,%1,%2,%3}, {%4,%5,%6,%7}, {%8,%9}, {%0,%1,%2,%3};"
        : "+f"(d[0]), "+f"(d[1]), "+f"(d[2]), "+f"(d[3])
        : "r"(a0), "r"(a1), "r"(a2), "r"(a3), "r"(b0), "r"(b1));
}

// 8x8 B fragment (col-major k8 x n8) from global W[k][n], fp16 (hi only)
__device__ __forceinline__ uint32_t make_hfrag(const float* __restrict__ W, int ldn,
                                               int k0, int n0, int lane) {
    int g = lane >> 2, tg = lane & 3;
    const float* p = W + (size_t)(k0 + tg * 2) * ldn + (n0 + g);
    return pkh2(p[0], p[ldn]);
}

__global__ void __launch_bounds__(TPB, 2)
regressor_mma_kernel(const float* __restrict__ x_src,
                     const float* __restrict__ x_dst,
                     const int* __restrict__ eidx,
                     const float* __restrict__ ew1, const float* __restrict__ eb1,
                     const float* __restrict__ ww1, const float* __restrict__ wb1,
                     const float* __restrict__ ew2, const float* __restrict__ eb2,
                     const float* __restrict__ ww2, const float* __restrict__ wb2,
                     const float* __restrict__ ew3, const float* __restrict__ eb3,
                     const float* __restrict__ ww3, const float* __restrict__ wb3,
                     const float* __restrict__ ew4, const float* __restrict__ eb4,
                     const float* __restrict__ ww4, const float* __restrict__ wb4,
                     float* __restrict__ out) {
    extern __shared__ char smem[];
    const uint32_t smb = smem_u32(smem);
    const int tid = threadIdx.x;
    const int wid = tid >> 5, lane = tid & 31;

    // warp roles within this CTA (8 warps)
    const int nw1 = wid * 16;              // L1: 16-col slice of fused 128
    const int branch = wid >> 2;           // L2/L3: 0 = exists, 1 = weight
    const int w4 = wid & 3;
    const int nL = w4 * 16;                // L2: 16-col slice of branch's 64
    const int mg = w4 >> 1;                // L3 m-group (4 mt each)
    const int ns3 = w4 & 1;                // L3 n-slice index
    const int n3 = ns3 * 16;               // L3 16-col n-slice

    // ---------- per-warp weight fragments (fp16 hi, registers) ----------
    const float* W2 = branch ? ww2 : ew2;  // [64][64]
    const float* W3 = branch ? ww3 : ew3;  // [64][32]
    const float* B2 = branch ? wb2 : eb2;
    const float* B3 = branch ? wb3 : eb3;
    const float* W4 = branch ? ww4 : ew4;

    // L1 fused weight fetch [128][128]: cols 0-63 = ew1, 64-127 = ww1
    uint32_t B1h[8][2][2];
#pragma unroll
    for (int kt = 0; kt < 8; kt++)
#pragma unroll
        for (int nt = 0; nt < 2; nt++)
#pragma unroll
            for (int r = 0; r < 2; r++) {
                int n0 = nw1 + nt * 8;
                const float* W = (n0 < 64) ? ew1 : ww1;
                B1h[kt][nt][r] = make_hfrag(W, 64, kt * 16 + r * 8, n0 & 63, lane);
            }

    uint32_t B2h[4][2][2];
#pragma unroll
    for (int kt = 0; kt < 4; kt++)
#pragma unroll
        for (int nt = 0; nt < 2; nt++)
#pragma unroll
            for (int r = 0; r < 2; r++)
                B2h[kt][nt][r] = make_hfrag(W2, 64, kt * 16 + r * 8, nL + nt * 8, lane);

    uint32_t B3h[4][2][2];
#pragma unroll
    for (int kt = 0; kt < 4; kt++)
#pragma unroll
        for (int nt = 0; nt < 2; nt++)
#pragma unroll
            for (int r = 0; r < 2; r++)
                B3h[kt][nt][r] = make_hfrag(W3, 32, kt * 16 + r * 8, n3 + nt * 8, lane);

    // per-thread biases / final weights for covered columns
    float b1v[2][2], b2v[2][2], b3v[2][2], w4v[2][2];
#pragma unroll
    for (int nt = 0; nt < 2; nt++)
#pragma unroll
        for (int j = 0; j < 2; j++) {
            int c1 = nw1 + nt * 8 + (lane & 3) * 2 + j;
            b1v[nt][j] = (c1 < 64) ? eb1[c1] : wb1[c1 - 64];
            int c2 = nL + nt * 8 + (lane & 3) * 2 + j;
            b2v[nt][j] = B2[c2];
            int c3 = n3 + nt * 8 + (lane & 3) * 2 + j;
            b3v[nt][j] = B3[c3];
            w4v[nt][j] = W4[c3];
        }
    if (tid == 0) {
        *(float*)(smem + SM_B4 + 0) = eb4[0];
        *(float*)(smem + SM_B4 + 4) = wb4[0];
    }
    __syncthreads();

    const uint32_t xb = smb + SM_X;
    const uint32_t yb = smb + SM_Y;

    for (int t = blockIdx.x; t < NTILES; t += gridDim.x) {
        // ===== gather: warp w owns edges [16w,16w+16); lanes 0-15 src, 16-31 dst =====
        {
            const int half = lane >> 4;
            const int c16 = lane & 15;
#pragma unroll 4
            for (int i = 0; i < 16; i++) {
                int m = wid * 16 + i;
                int e = t * TILE_M + m;
                int idx = half ? eidx[NEDGES + e] : eidx[e];
                const float* row = (half ? x_dst : x_src) + (size_t)idx * 64;
                float4 v = ((const float4*)row)[c16];
                uint32_t h0 = pkh2(v.x, v.y);
                uint32_t h1 = pkh2(v.z, v.w);
                uint32_t off = (uint32_t)m * ROWB + half * 128u + c16 * 8u;
                *(uint2*)(smem + SM_X + off) = make_uint2(h0, h1);
            }
        }
        __syncthreads();

        // ===== L1: X[128x128] -> Y[128x128]; warp: 16-col slice, all m =====
        {
#pragma unroll 1
            for (int mt = 0; mt < 8; mt++) {
                int m0 = mt * 16;
                float aP[2][4] = {};
                uint32_t arow = (uint32_t)(m0 + (lane & 15)) * ROWB + (lane >> 4) * 16u;
#pragma unroll
                for (int kt = 0; kt < 8; kt++) {
                    uint32_t h0, h1, h2, h3;
                    ldsm4(xb + arow + kt * 32u, h0, h1, h2, h3);
                    mma16816(aP[0], h0, h1, h2, h3, B1h[kt][0][0], B1h[kt][0][1]);
                    mma16816(aP[1], h0, h1, h2, h3, B1h[kt][1][0], B1h[kt][1][1]);
                }
#pragma unroll
                for (int nt = 0; nt < 2; nt++) {
                    float v0 = lrelu(aP[nt][0] + b1v[nt][0]);
                    float v1 = lrelu(aP[nt][1] + b1v[nt][1]);
                    float v2 = lrelu(aP[nt][2] + b1v[nt][0]);
                    float v3 = lrelu(aP[nt][3] + b1v[nt][1]);
                    uint32_t col2 = (uint32_t)(nw1 + nt * 8 + (lane & 3) * 2) * 2u;
                    uint32_t o0 = (uint32_t)(m0 + (lane >> 2)) * ROWB + col2;
                    uint32_t o1 = (uint32_t)(m0 + 8 + (lane >> 2)) * ROWB + col2;
                    *(uint32_t*)(smem + SM_Y + o0) = pkh2(v0, v1);
                    *(uint32_t*)(smem + SM_Y + o1) = pkh2(v2, v3);
                }
            }
        }
        __syncthreads();

        // ===== L2: Y (cols branch*64..) -> X (cols branch*64..) =====
        {
            const int colout = branch * 64 + nL;
            const uint32_t abase = (uint32_t)branch * 128u;
#pragma unroll 1
            for (int mt = 0; mt < 8; mt++) {
                int m0 = mt * 16;
                float aP[2][4] = {};
                uint32_t arow = (uint32_t)(m0 + (lane & 15)) * ROWB + abase + (lane >> 4) * 16u;
#pragma unroll
                for (int kt = 0; kt < 4; kt++) {
                    uint32_t h0, h1, h2, h3;
                    ldsm4(yb + arow + kt * 32u, h0, h1, h2, h3);
                    mma16816(aP[0], h0, h1, h2, h3, B2h[kt][0][0], B2h[kt][0][1]);
                    mma16816(aP[1], h0, h1, h2, h3, B2h[kt][1][0], B2h[kt][1][1]);
                }
#pragma unroll
                for (int nt = 0; nt < 2; nt++) {
                    float v0 = lrelu(aP[nt][0] + b2v[nt][0]);
                    float v1 = lrelu(aP[nt][1] + b2v[nt][1]);
                    float v2 = lrelu(aP[nt][2] + b2v[nt][0]);
                    float v3 = lrelu(aP[nt][3] + b2v[nt][1]);
                    uint32_t col2 = (uint32_t)(colout + nt * 8 + (lane & 3) * 2) * 2u;
                    uint32_t o0 = (uint32_t)(m0 + (lane >> 2)) * ROWB + col2;
                    uint32_t o1 = (uint32_t)(m0 + 8 + (lane >> 2)) * ROWB + col2;
                    *(uint32_t*)(smem + SM_X + o0) = pkh2(v0, v1);
                    *(uint32_t*)(smem + SM_X + o1) = pkh2(v2, v3);
                }
            }
        }
        __syncthreads();

        // ===== L3 + L4: X (cols branch*64..) -> partials in P =====
        {
            const uint32_t abase = (uint32_t)branch * 128u;
            float* P = (float*)(smem + SM_P);
#pragma unroll 1
            for (int i = 0; i < 4; i++) {
                int m0 = (mg * 4 + i) * 16;
                float aP[2][4] = {};
                uint32_t arow = (uint32_t)(m0 + (lane & 15)) * ROWB + abase + (lane >> 4) * 16u;
#pragma unroll
                for (int kt = 0; kt < 4; kt++) {
                    uint32_t h0, h1, h2, h3;
                    ldsm4(xb + arow + kt * 32u, h0, h1, h2, h3);
                    mma16816(aP[0], h0, h1, h2, h3, B3h[kt][0][0], B3h[kt][0][1]);
                    mma16816(aP[1], h0, h1, h2, h3, B3h[kt][1][0], B3h[kt][1][1]);
                }
                float p0 = 0.0f, p1 = 0.0f;
#pragma unroll
                for (int nt = 0; nt < 2; nt++) {
                    p0 += lrelu(aP[nt][0] + b3v[nt][0]) * w4v[nt][0] +
                          lrelu(aP[nt][1] + b3v[nt][1]) * w4v[nt][1];
                    p1 += lrelu(aP[nt][2] + b3v[nt][0]) * w4v[nt][0] +
                          lrelu(aP[nt][3] + b3v[nt][1]) * w4v[nt][1];
                }
                p0 += __shfl_xor_sync(0xFFFFFFFFu, p0, 1);
                p0 += __shfl_xor_sync(0xFFFFFFFFu, p0, 2);
                p1 += __shfl_xor_sync(0xFFFFFFFFu, p1, 1);
                p1 += __shfl_xor_sync(0xFFFFFFFFu, p1, 2);
                if ((lane & 3) == 0) {
                    int r0 = m0 + (lane >> 2);
                    P[((branch << 7) + r0) * 2 + ns3] = p0;
                    P[((branch << 7) + r0 + 8) * 2 + ns3] = p1;
                }
            }
        }
        __syncthreads();

        // ===== final reduce + store (256 threads = whole CTA) =====
        {
            int br = tid >> 7, m = tid & 127;
            float2 pv = *(const float2*)(smem + SM_P + ((br << 7) + m) * 8);
            float b4 = *(const float*)(smem + SM_B4 + br * 4);
            out[br * NEDGES + t * TILE_M + m] = pv.x + pv.y + b4;
        }
        // hazards: next gather writes X — last X readers (L3 ldmatrix) done
        // before the sync above; P is rewritten only after 3 more syncs.
    }
}

extern "C" void kernel_launch(void* const* d_in, const int* in_sizes, int n_in,
                              void* d_out, int out_size) {
    const float* x_src = (const float*)d_in[0];
    const float* x_dst = (const float*)d_in[1];
    const int* eidx = (const int*)d_in[2];
    const float* ew1 = (const float*)d_in[3];
    const float* eb1 = (const float*)d_in[4];
    const float* ww1 = (const float*)d_in[5];
    const float* wb1 = (const float*)d_in[6];
    const float* ew2 = (const float*)d_in[7];
    const float* eb2 = (const float*)d_in[8];
    const float* ww2 = (const float*)d_in[9];
    const float* wb2 = (const float*)d_in[10];
    const float* ew3 = (const float*)d_in[11];
    const float* eb3 = (const float*)d_in[12];
    const float* ww3 = (const float*)d_in[13];
    const float* wb3 = (const float*)d_in[14];
    const float* ew4 = (const float*)d_in[15];
    const float* eb4 = (const float*)d_in[16];
    const float* ww4 = (const float*)d_in[17];
    const float* wb4 = (const float*)d_in[18];
    float* out = (float*)d_out;

    int nsm = 148;
    cudaDeviceGetAttribute(&nsm, cudaDevAttrMultiProcessorCount, 0);

    cudaFuncSetAttribute(regressor_mma_kernel,
                         cudaFuncAttributeMaxDynamicSharedMemorySize, SMEM_BYTES);

    regressor_mma_kernel<<<2 * nsm, TPB, SMEM_BYTES>>>(
        x_src, x_dst, eidx, ew1, eb1, ww1, wb1, ew2, eb2, ww2, wb2,
        ew3, eb3, ww3, wb3, ew4, eb4, ww4, wb4, out);
}

// round 14
// speedup vs baseline: 1.1762x; 1.0127x over previous
#include <cuda_runtime.h>
#include <cuda_fp16.h>
#include <cstdint>

#define NEDGES 2000000
#define TILE_M 128
#define NTILES (NEDGES / TILE_M)
#define TPB 256

// X, Y: [128 rows][136 fp16] stride 272 B (17*16: conflict-free ldmatrix)
#define ROWB 272
#define SM_X  0                 // 34816 B
#define SM_Y  34816             // 34816 B
#define SM_P  69632             // float[2][128][2] = 2048 B
#define SM_B4 71680             // float[2]
#define SMEM_BYTES 71744

// branch-local barrier: 4 warps = 128 threads, ids 1 / 2
#define BRANCH_BAR(b) \
    asm volatile("bar.sync %0, %1;" :: "r"(1 + (b)), "r"(128) : "memory")

__device__ __forceinline__ uint32_t smem_u32(const void* p) {
    uint32_t a;
    asm("{ .reg .u64 t; cvta.to.shared.u64 t, %1; cvt.u32.u64 %0, t; }" : "=r"(a) : "l"(p));
    return a;
}
__device__ __forceinline__ float lrelu(float z) { return fmaxf(z, 0.01f * z); }

// pack 2 f32 -> fp16x2 (a in low half)
__device__ __forceinline__ uint32_t pkh2(float a, float b) {
    __half2 h = __floats2half2_rn(a, b);
    return *(uint32_t*)&h;
}

__device__ __forceinline__ void ldsm4(uint32_t addr, uint32_t& a0, uint32_t& a1,
                                      uint32_t& a2, uint32_t& a3) {
    asm volatile("ldmatrix.sync.aligned.m8n8.x4.shared.b16 {%0,%1,%2,%3}, [%4];"
                 : "=r"(a0), "=r"(a1), "=r"(a2), "=r"(a3) : "r"(addr));
}
__device__ __forceinline__ void mma16816(float* d, uint32_t a0, uint32_t a1,
                                         uint32_t a2, uint32_t a3,
                                         uint32_t b0, uint32_t b1) {
    asm volatile(
        "mma.sync.aligned.m16n8k16.row.col.f32.f16.f16.f32 "
        "{%0,%1,%2,%3}, {%4,%5,%6,%7}, {%8,%9}, {%0,%1,%2,%3};"
        : "+f"(d[0]), "+f"(d[1]), "+f"(d[2]), "+f"(d[3])
        : "r"(a0), "r"(a1), "r"(a2), "r"(a3), "r"(b0), "r"(b1));
}

// 8x8 B fragment (col-major k8 x n8) from global W[k][n], fp16 (hi only)
__device__ __forceinline__ uint32_t make_hfrag(const float* __restrict__ W, int ldn,
                                               int k0, int n0, int lane) {
    int g = lane >> 2, tg = lane & 3;
    const float* p = W + (size_t)(k0 + tg * 2) * ldn + (n0 + g);
    return pkh2(p[0], p[ldn]);
}

__global__ void __launch_bounds__(TPB, 2)
regressor_mma_kernel(const float* __restrict__ x_src,
                     const float* __restrict__ x_dst,
                     const int* __restrict__ eidx,
                     const float* __restrict__ ew1, const float* __restrict__ eb1,
                     const float* __restrict__ ww1, const float* __restrict__ wb1,
                     const float* __restrict__ ew2, const float* __restrict__ eb2,
                     const float* __restrict__ ww2, const float* __restrict__ wb2,
                     const float* __restrict__ ew3, const float* __restrict__ eb3,
                     const float* __restrict__ ww3, const float* __restrict__ wb3,
                     const float* __restrict__ ew4, const float* __restrict__ eb4,
                     const float* __restrict__ ww4, const float* __restrict__ wb4,
                     float* __restrict__ out) {
    extern __shared__ char smem[];
    const uint32_t smb = smem_u32(smem);
    const int tid = threadIdx.x;
    const int wid = tid >> 5, lane = tid & 31;

    // warp roles within this CTA (8 warps)
    const int nw1 = wid * 16;              // L1: 16-col slice of fused 128
    const int branch = wid >> 2;           // L2/L3: 0 = exists, 1 = weight
    const int w4 = wid & 3;
    const int nL = w4 * 16;                // L2: 16-col slice of branch's 64
    const int mg = w4 >> 1;                // L3 m-group (4 mt each)
    const int ns3 = w4 & 1;                // L3 n-slice index
    const int n3 = ns3 * 16;               // L3 16-col n-slice

    // ---------- per-warp weight fragments (fp16 hi, registers) ----------
    const float* W2 = branch ? ww2 : ew2;  // [64][64]
    const float* W3 = branch ? ww3 : ew3;  // [64][32]
    const float* B2 = branch ? wb2 : eb2;
    const float* B3 = branch ? wb3 : eb3;
    const float* W4 = branch ? ww4 : ew4;

    // L1 fused weight fetch [128][128]: cols 0-63 = ew1, 64-127 = ww1
    uint32_t B1h[8][2][2];
#pragma unroll
    for (int kt = 0; kt < 8; kt++)
#pragma unroll
        for (int nt = 0; nt < 2; nt++)
#pragma unroll
            for (int r = 0; r < 2; r++) {
                int n0 = nw1 + nt * 8;
                const float* W = (n0 < 64) ? ew1 : ww1;
                B1h[kt][nt][r] = make_hfrag(W, 64, kt * 16 + r * 8, n0 & 63, lane);
            }

    uint32_t B2h[4][2][2];
#pragma unroll
    for (int kt = 0; kt < 4; kt++)
#pragma unroll
        for (int nt = 0; nt < 2; nt++)
#pragma unroll
            for (int r = 0; r < 2; r++)
                B2h[kt][nt][r] = make_hfrag(W2, 64, kt * 16 + r * 8, nL + nt * 8, lane);

    uint32_t B3h[4][2][2];
#pragma unroll
    for (int kt = 0; kt < 4; kt++)
#pragma unroll
        for (int nt = 0; nt < 2; nt++)
#pragma unroll
            for (int r = 0; r < 2; r++)
                B3h[kt][nt][r] = make_hfrag(W3, 32, kt * 16 + r * 8, n3 + nt * 8, lane);

    // per-thread biases / final weights for covered columns
    float b1v[2][2], b2v[2][2], b3v[2][2], w4v[2][2];
#pragma unroll
    for (int nt = 0; nt < 2; nt++)
#pragma unroll
        for (int j = 0; j < 2; j++) {
            int c1 = nw1 + nt * 8 + (lane & 3) * 2 + j;
            b1v[nt][j] = (c1 < 64) ? eb1[c1] : wb1[c1 - 64];
            int c2 = nL + nt * 8 + (lane & 3) * 2 + j;
            b2v[nt][j] = B2[c2];
            int c3 = n3 + nt * 8 + (lane & 3) * 2 + j;
            b3v[nt][j] = B3[c3];
            w4v[nt][j] = W4[c3];
        }
    if (tid == 0) {
        *(float*)(smem + SM_B4 + 0) = eb4[0];
        *(float*)(smem + SM_B4 + 4) = wb4[0];
    }
    __syncthreads();

    const uint32_t xb = smb + SM_X;
    const uint32_t yb = smb + SM_Y;

    for (int t = blockIdx.x; t < NTILES; t += gridDim.x) {
        // ===== gather: warp w owns edges [16w,16w+16); lanes 0-15 src, 16-31 dst =====
        {
            const int half = lane >> 4;
            const int c16 = lane & 15;
#pragma unroll 4
            for (int i = 0; i < 16; i++) {
                int m = wid * 16 + i;
                int e = t * TILE_M + m;
                int idx = half ? eidx[NEDGES + e] : eidx[e];
                const float* row = (half ? x_dst : x_src) + (size_t)idx * 64;
                float4 v = ((const float4*)row)[c16];
                uint32_t h0 = pkh2(v.x, v.y);
                uint32_t h1 = pkh2(v.z, v.w);
                uint32_t off = (uint32_t)m * ROWB + half * 128u + c16 * 8u;
                *(uint2*)(smem + SM_X + off) = make_uint2(h0, h1);
            }
        }
        __syncthreads();   // all warps read all of X in L1

        // ===== L1: X[128x128] -> Y[128x128]; warp: 16-col slice, all m =====
        {
#pragma unroll 1
            for (int mt = 0; mt < 8; mt++) {
                int m0 = mt * 16;
                float aP[2][4] = {};
                uint32_t arow = (uint32_t)(m0 + (lane & 15)) * ROWB + (lane >> 4) * 16u;
#pragma unroll
                for (int kt = 0; kt < 8; kt++) {
                    uint32_t h0, h1, h2, h3;
                    ldsm4(xb + arow + kt * 32u, h0, h1, h2, h3);
                    mma16816(aP[0], h0, h1, h2, h3, B1h[kt][0][0], B1h[kt][0][1]);
                    mma16816(aP[1], h0, h1, h2, h3, B1h[kt][1][0], B1h[kt][1][1]);
                }
#pragma unroll
                for (int nt = 0; nt < 2; nt++) {
                    float v0 = lrelu(aP[nt][0] + b1v[nt][0]);
                    float v1 = lrelu(aP[nt][1] + b1v[nt][1]);
                    float v2 = lrelu(aP[nt][2] + b1v[nt][0]);
                    float v3 = lrelu(aP[nt][3] + b1v[nt][1]);
                    uint32_t col2 = (uint32_t)(nw1 + nt * 8 + (lane & 3) * 2) * 2u;
                    uint32_t o0 = (uint32_t)(m0 + (lane >> 2)) * ROWB + col2;
                    uint32_t o1 = (uint32_t)(m0 + 8 + (lane >> 2)) * ROWB + col2;
                    *(uint32_t*)(smem + SM_Y + o0) = pkh2(v0, v1);
                    *(uint32_t*)(smem + SM_Y + o1) = pkh2(v2, v3);
                }
            }
        }
        // L1 -> L2 is branch-local: branch b's L2 warps read Y cols [64b,64b+64),
        // which were written exactly by L1 warps 4b..4b+3 (warp w wrote cols 16w).
        BRANCH_BAR(branch);

        // ===== L2: Y (cols branch*64..) -> X (cols branch*64..) =====
        {
            const int colout = branch * 64 + nL;
            const uint32_t abase = (uint32_t)branch * 128u;
#pragma unroll 1
            for (int mt = 0; mt < 8; mt++) {
                int m0 = mt * 16;
                float aP[2][4] = {};
                uint32_t arow = (uint32_t)(m0 + (lane & 15)) * ROWB + abase + (lane >> 4) * 16u;
#pragma unroll
                for (int kt = 0; kt < 4; kt++) {
                    uint32_t h0, h1, h2, h3;
                    ldsm4(yb + arow + kt * 32u, h0, h1, h2, h3);
                    mma16816(aP[0], h0, h1, h2, h3, B2h[kt][0][0], B2h[kt][0][1]);
                    mma16816(aP[1], h0, h1, h2, h3, B2h[kt][1][0], B2h[kt][1][1]);
                }
#pragma unroll
                for (int nt = 0; nt < 2; nt++) {
                    float v0 = lrelu(aP[nt][0] + b2v[nt][0]);
                    float v1 = lrelu(aP[nt][1] + b2v[nt][1]);
                    float v2 = lrelu(aP[nt][2] + b2v[nt][0]);
                    float v3 = lrelu(aP[nt][3] + b2v[nt][1]);
                    uint32_t col2 = (uint32_t)(colout + nt * 8 + (lane & 3) * 2) * 2u;
                    uint32_t o0 = (uint32_t)(m0 + (lane >> 2)) * ROWB + col2;
                    uint32_t o1 = (uint32_t)(m0 + 8 + (lane >> 2)) * ROWB + col2;
                    *(uint32_t*)(smem + SM_X + o0) = pkh2(v0, v1);
                    *(uint32_t*)(smem + SM_X + o1) = pkh2(v2, v3);
                }
            }
        }
        // L2 -> L3 branch-local: branch b's L3 reads X cols [64b,..) written by
        // branch b's own L2 warps.
        BRANCH_BAR(branch);

        // ===== L3 + L4: X (cols branch*64..) -> partials in P =====
        {
            const uint32_t abase = (uint32_t)branch * 128u;
            float* P = (float*)(smem + SM_P);
#pragma unroll 1
            for (int i = 0; i < 4; i++) {
                int m0 = (mg * 4 + i) * 16;
                float aP[2][4] = {};
                uint32_t arow = (uint32_t)(m0 + (lane & 15)) * ROWB + abase + (lane >> 4) * 16u;
#pragma unroll
                for (int kt = 0; kt < 4; kt++) {
                    uint32_t h0, h1, h2, h3;
                    ldsm4(xb + arow + kt * 32u, h0, h1, h2, h3);
                    mma16816(aP[0], h0, h1, h2, h3, B3h[kt][0][0], B3h[kt][0][1]);
                    mma16816(aP[1], h0, h1, h2, h3, B3h[kt][1][0], B3h[kt][1][1]);
                }
                float p0 = 0.0f, p1 = 0.0f;
#pragma unroll
                for (int nt = 0; nt < 2; nt++) {
                    p0 += lrelu(aP[nt][0] + b3v[nt][0]) * w4v[nt][0] +
                          lrelu(aP[nt][1] + b3v[nt][1]) * w4v[nt][1];
                    p1 += lrelu(aP[nt][2] + b3v[nt][0]) * w4v[nt][0] +
                          lrelu(aP[nt][3] + b3v[nt][1]) * w4v[nt][1];
                }
                p0 += __shfl_xor_sync(0xFFFFFFFFu, p0, 1);
                p0 += __shfl_xor_sync(0xFFFFFFFFu, p0, 2);
                p1 += __shfl_xor_sync(0xFFFFFFFFu, p1, 1);
                p1 += __shfl_xor_sync(0xFFFFFFFFu, p1, 2);
                if ((lane & 3) == 0) {
                    int r0 = m0 + (lane >> 2);
                    P[((branch << 7) + r0) * 2 + ns3] = p0;
                    P[((branch << 7) + r0 + 8) * 2 + ns3] = p1;
                }
            }
        }
        // L3 -> store branch-local: P half b written by branch b warps, read by
        // tids [128b,128b+128) below.
        BRANCH_BAR(branch);

        // ===== final reduce + store (256 threads = whole CTA) =====
        {
            int br = tid >> 7, m = tid & 127;
            float2 pv = *(const float2*)(smem + SM_P + ((br << 7) + m) * 8);
            float b4 = *(const float*)(smem + SM_B4 + br * 4);
            out[br * NEDGES + t * TILE_M + m] = pv.x + pv.y + b4;
        }
        __syncthreads();   // cross-branch: next gather overwrites X rows that the
                           // OTHER branch's L3 was reading; join both branches here.
    }
}

extern "C" void kernel_launch(void* const* d_in, const int* in_sizes, int n_in,
                              void* d_out, int out_size) {
    const float* x_src = (const float*)d_in[0];
    const float* x_dst = (const float*)d_in[1];
    const int* eidx = (const int*)d_in[2];
    const float* ew1 = (const float*)d_in[3];
    const float* eb1 = (const float*)d_in[4];
    const float* ww1 = (const float*)d_in[5];
    const float* wb1 = (const float*)d_in[6];
    const float* ew2 = (const float*)d_in[7];
    const float* eb2 = (const float*)d_in[8];
    const float* ww2 = (const float*)d_in[9];
    const float* wb2 = (const float*)d_in[10];
    const float* ew3 = (const float*)d_in[11];
    const float* eb3 = (const float*)d_in[12];
    const float* ww3 = (const float*)d_in[13];
    const float* wb3 = (const float*)d_in[14];
    const float* ew4 = (const float*)d_in[15];
    const float* eb4 = (const float*)d_in[16];
    const float* ww4 = (const float*)d_in[17];
    const float* wb4 = (const float*)d_in[18];
    float* out = (float*)d_out;

    int nsm = 148;
    cudaDeviceGetAttribute(&nsm, cudaDevAttrMultiProcessorCount, 0);

    cudaFuncSetAttribute(regressor_mma_kernel,
                         cudaFuncAttributeMaxDynamicSharedMemorySize, SMEM_BYTES);

    regressor_mma_kernel<<<2 * nsm, TPB, SMEM_BYTES>>>(
        x_src, x_dst, eidx, ew1, eb1, ww1, wb1, ew2, eb2, ww2, wb2,
        ew3, eb3, ww3, wb3, ew4, eb4, ww4, wb4, out);
}